// round 13
// baseline (speedup 1.0000x reference)
#include <cuda_runtime.h>
#include <cstdint>

#define SLOPE 0.01f
#define EPSBN 1e-5f
#define NPOS  65536

// ---------------- device scratch ----------------
// A-fragment tables: [layer][split][16kc * 8mt * 32lane * 4regs] tf32 bit patterns
__device__ uint32_t g_wA[4][3][16384];
__device__ float g_b1[128], g_br[128], g_b2[128], g_b3[128], g_wm[128];
__device__ float g_bm;
__device__ float4 g_moe4[131072];   // [expert][c/4][lane]

__device__ __forceinline__ float lrelu(float v) { return v >= 0.0f ? v : SLOPE * v; }

__device__ __forceinline__ uint32_t tf32_of(float x) {
    uint32_t r;
    asm("cvt.rna.tf32.f32 %0, %1;" : "=r"(r) : "f"(x));
    return r;
}

// m16n8k8 tf32 mma, D==C accumulate in place
__device__ __forceinline__ void mma8(float* c, const uint4 a, uint32_t b0, uint32_t b1) {
    asm volatile(
        "mma.sync.aligned.m16n8k8.row.col.f32.tf32.tf32.f32 "
        "{%0,%1,%2,%3}, {%4,%5,%6,%7}, {%8,%9}, {%0,%1,%2,%3};"
        : "+f"(c[0]), "+f"(c[1]), "+f"(c[2]), "+f"(c[3])
        : "r"(a.x), "r"(a.y), "r"(a.z), "r"(a.w), "r"(b0), "r"(b1));
}

// ---------------- prep: fold BN, bake A-fragment tables, MoE repack ----------------
__global__ void prep_kernel(const float* __restrict__ cl1_w, const float* __restrict__ cl1_b,
                            const float* __restrict__ g1,    const float* __restrict__ be1,
                            const float* __restrict__ m1,    const float* __restrict__ v1,
                            const float* __restrict__ cl2_w, const float* __restrict__ cl2_b,
                            const float* __restrict__ cl3_w, const float* __restrict__ cl3_b,
                            const float* __restrict__ reg1_w,const float* __restrict__ reg1_b,
                            const float* __restrict__ gr,    const float* __restrict__ ber,
                            const float* __restrict__ mr,    const float* __restrict__ vr,
                            const float* __restrict__ cm2_w)
{
    int tid = blockIdx.x * blockDim.x + threadIdx.x;   // 0..131071

    // MoE repack
    {
        int e  = tid >> 10;
        int cg = (tid >> 5) & 31;
        int j  = tid & 31;
        const float* src = cm2_w + e * 4096 + (cg * 4) * 32 + j;
        g_moe4[tid] = make_float4(src[0], src[32], src[64], src[96]);
    }

    if (tid < 65536) {
        int l = tid >> 14, o = (tid >> 7) & 127, k = tid & 127;
        float wv;
        if (l == 0)      wv = cl1_w[o * 128 + k] * (g1[o] * rsqrtf(v1[o] + EPSBN));
        else if (l == 1) wv = reg1_w[o * 128 + k] * (gr[o] * rsqrtf(vr[o] + EPSBN));
        else if (l == 2) wv = cl2_w[o * 128 + k];
        else             wv = cl3_w[o * 128 + k];
        // 3-way tf32 split
        uint32_t sh = tf32_of(wv);
        float r1v = wv - __uint_as_float(sh);
        uint32_t smid = tf32_of(r1v);
        uint32_t sl = tf32_of(r1v - __uint_as_float(smid));
        // fragment slot: documented m16n8k8 A layout
        int mtg = o >> 4;             // 0..7
        int g   = o & 7, h = (o >> 3) & 1;
        int kc  = k >> 3, tig = k & 3, kh = (k >> 2) & 1;
        int lane = g * 4 + tig, reg = h + 2 * kh;
        int fi = (kc * 8 + mtg) * 128 + lane * 4 + reg;
        g_wA[l][0][fi] = sh;
        g_wA[l][1][fi] = smid;
        g_wA[l][2][fi] = sl;
    }
    if (tid < 128) {
        float s = g1[tid] * rsqrtf(v1[tid] + EPSBN);
        g_b1[tid] = cl1_b[tid] * s + be1[tid] - m1[tid] * s;
        float s2 = gr[tid] * rsqrtf(vr[tid] + EPSBN);
        g_br[tid] = reg1_b[tid] * s2 + ber[tid] - mr[tid] * s2;
        g_b2[tid] = cl2_b[tid];
        g_b3[tid] = cl3_b[tid];
        g_wm[tid] = cl3_w[128 * 128 + tid];
        if (tid == 0) g_bm = cl3_b[128];
    }
}

// ---------------- 128x128 x 64 GEMM via mma.sync tf32 ----------------
// Warp w: channels 32w..32w+31 (2 M-tiles), positions 0..63 (8 N-tiles).
// sIn: fp32 activation tile [128 ch][72] (conflict-free B loads).
// NS=3: 6-product split (~2^-33);  NS=1: hi-only (~2^-10, xr path).
template<int NS>
__device__ __forceinline__ void gemm_mma(const uint4* __restrict__ A0,
                                         const uint4* __restrict__ A1,
                                         const uint4* __restrict__ A2,
                                         const float* __restrict__ sIn,
                                         float acc[2][8][4], int w, int lane)
{
    const int g = lane >> 2, tig = lane & 3;
#pragma unroll
    for (int mt = 0; mt < 2; mt++)
#pragma unroll
        for (int n = 0; n < 8; n++)
#pragma unroll
            for (int c = 0; c < 4; c++) acc[mt][n][c] = 0.0f;

    uint4 Ab[2][2][NS];
    {
        int fo = (2 * w) * 32 + lane;
#pragma unroll
        for (int mt = 0; mt < 2; mt++) {
            Ab[0][mt][0] = __ldg(A0 + fo + mt * 32);
            if (NS > 1) {
                Ab[0][mt][1] = __ldg(A1 + fo + mt * 32);
                Ab[0][mt][2] = __ldg(A2 + fo + mt * 32);
            }
        }
    }

#pragma unroll 1
    for (int kc = 0; kc < 16; kc++) {
        int cur = kc & 1;
        if (kc < 15) {
            int fo = ((kc + 1) * 8 + 2 * w) * 32 + lane;
#pragma unroll
            for (int mt = 0; mt < 2; mt++) {
                Ab[cur ^ 1][mt][0] = __ldg(A0 + fo + mt * 32);
                if (NS > 1) {
                    Ab[cur ^ 1][mt][1] = __ldg(A1 + fo + mt * 32);
                    Ab[cur ^ 1][mt][2] = __ldg(A2 + fo + mt * 32);
                }
            }
        }
        const float* bp = sIn + (kc * 8 + tig) * 72 + g;
#pragma unroll
        for (int n = 0; n < 8; n++) {
            float x0 = bp[8 * n], x1 = bp[288 + 8 * n];
            uint32_t h0 = tf32_of(x0), h1 = tf32_of(x1);
            if (NS == 1) {
#pragma unroll
                for (int mt = 0; mt < 2; mt++)
                    mma8(acc[mt][n], Ab[cur][mt][0], h0, h1);
            } else {
                float r0 = x0 - __uint_as_float(h0), r1 = x1 - __uint_as_float(h1);
                uint32_t m0 = tf32_of(r0), m1 = tf32_of(r1);
                uint32_t l0 = tf32_of(r0 - __uint_as_float(m0));
                uint32_t l1 = tf32_of(r1 - __uint_as_float(m1));
#pragma unroll
                for (int mt = 0; mt < 2; mt++) {
                    mma8(acc[mt][n], Ab[cur][mt][0], h0, h1);   // hh
                    mma8(acc[mt][n], Ab[cur][mt][0], m0, m1);   // hm
                    mma8(acc[mt][n], Ab[cur][mt][1], h0, h1);   // mh
                    mma8(acc[mt][n], Ab[cur][mt][0], l0, l1);   // hl
                    mma8(acc[mt][n], Ab[cur][mt][2], h0, h1);   // lh
                    mma8(acc[mt][n], Ab[cur][mt][1], m0, m1);   // mm
                }
            }
        }
    }
}

// epilogue: lrelu(acc + bias) -> sY[ch][72]
__device__ __forceinline__ void epi_storeY(float* sY, const float* bias,
                                           float acc[2][8][4], int w, int lane)
{
    const int g = lane >> 2, tig = lane & 3;
#pragma unroll
    for (int mt = 0; mt < 2; mt++)
#pragma unroll
        for (int h = 0; h < 2; h++) {
            int ch = 32 * w + 16 * mt + g + 8 * h;
            float bi = bias[ch];
#pragma unroll
            for (int n = 0; n < 8; n++) {
                float v0 = lrelu(acc[mt][n][2 * h]     + bi);
                float v1 = lrelu(acc[mt][n][2 * h + 1] + bi);
                *(float2*)(sY + ch * 72 + 8 * n + 2 * tig) = make_float2(v0, v1);
            }
        }
}

// ---------------- fused main kernel (128 threads, 3 CTAs/SM) ----------------
__global__ void __launch_bounds__(128, 3)
fused_kernel(const float* __restrict__ x_in,
             const float* __restrict__ cm2_b,
             const float* __restrict__ cm3_w, const float* __restrict__ cm3_b,
             float* __restrict__ out)
{
    extern __shared__ float sm[];
    float* sX   = sm;                 // [128][72] fp32 x tile (9216 floats)
    float* sXR  = sm;                 // [64][132] fp32 xr (aliases sX after R1)
    float* sY   = sm + 9216;          // [128][72] y1/y2 tile
    float* sRv  = sm + 18432;         // 4*64 argmax vals
    int*   sRi  = (int*)(sm + 18688); // 4*64 argmax idx
    int*   sInd = (int*)(sm + 18944); // 64

    const int t = threadIdx.x, w = t >> 5, lane = t & 31;
    const int g = lane >> 2, tig = lane & 3;
    const int bb = blockIdx.x >> 7;
    const int w0 = (blockIdx.x & 127) * 64;
    const float* xb = x_in + (size_t)bb * 128 * 8192 + w0;

    // stage x tile [ch][pos]
#pragma unroll
    for (int j = 0; j < 16; j++) {
        int idx = t + j * 128;
        int c = idx >> 4, p4 = idx & 15;
        float4 v = *(const float4*)(xb + c * 8192 + p4 * 4);
        *(float4*)(sX + c * 72 + p4 * 4) = v;
    }
    __syncthreads();   // (1) x visible

    float acc[2][8][4];
    const uint4* A0;
    const uint4* A1;
    const uint4* A2;

    // ---- L1: y1 (6-product) : sX -> sY ----
    A0 = (const uint4*)g_wA[0][0]; A1 = (const uint4*)g_wA[0][1]; A2 = (const uint4*)g_wA[0][2];
    gemm_mma<3>(A0, A1, A2, sX, acc, w, lane);
    epi_storeY(sY, g_b1, acc, w, lane);

    // ---- R1: xr (1-product) : sX -> sXR (aliases sX) ----
    A0 = (const uint4*)g_wA[1][0];
    gemm_mma<1>(A0, A0, A0, sX, acc, w, lane);
    __syncthreads();   // (2) all reads of sX + all writes of y1 done
#pragma unroll
    for (int mt = 0; mt < 2; mt++)
#pragma unroll
        for (int h = 0; h < 2; h++) {
            int ch = 32 * w + 16 * mt + g + 8 * h;
            float bi = g_br[ch];
#pragma unroll
            for (int n = 0; n < 8; n++) {
                int pos = 8 * n + 2 * tig;
                sXR[pos * 132 + ch]       = lrelu(acc[mt][n][2 * h]     + bi);
                sXR[(pos + 1) * 132 + ch] = lrelu(acc[mt][n][2 * h + 1] + bi);
            }
        }

    // ---- L2: y2 (6-product) : sY -> sY ----
    A0 = (const uint4*)g_wA[2][0]; A1 = (const uint4*)g_wA[2][1]; A2 = (const uint4*)g_wA[2][2];
    gemm_mma<3>(A0, A1, A2, sY, acc, w, lane);
    __syncthreads();   // (3) all warps done reading y1
    epi_storeY(sY, g_b2, acc, w, lane);
    __syncthreads();   // (4) y2 complete

    // ---- L3: logits (6-product) : sY -> acc ----
    A0 = (const uint4*)g_wA[3][0]; A1 = (const uint4*)g_wA[3][1]; A2 = (const uint4*)g_wA[3][2];
    gemm_mma<3>(A0, A1, A2, sY, acc, w, lane);

    // per-thread argmax over its 4 channels, per position (ascending ch -> first-occurrence)
    {
        float bv[8][2];
        int   bi[8][2];
#pragma unroll
        for (int n = 0; n < 8; n++)
#pragma unroll
            for (int lc = 0; lc < 2; lc++) {
                float best = acc[0][n][lc] + g_b3[32 * w + g];
                int   bidx = 32 * w + g;
#pragma unroll
                for (int cand = 1; cand < 4; cand++) {
                    int mt = cand >> 1, h = cand & 1;
                    int ch = 32 * w + 16 * mt + g + 8 * h;
                    float v = acc[mt][n][2 * h + lc] + g_b3[ch];
                    if (v > best) { best = v; bidx = ch; }
                }
                bv[n][lc] = best; bi[n][lc] = bidx;
            }
        // reduce over g-lanes (xor 4, 8, 16 keeps tig fixed)
#pragma unroll
        for (int off = 4; off <= 16; off <<= 1)
#pragma unroll
            for (int n = 0; n < 8; n++)
#pragma unroll
                for (int lc = 0; lc < 2; lc++) {
                    float ov = __shfl_xor_sync(0xffffffffu, bv[n][lc], off);
                    int   oi = __shfl_xor_sync(0xffffffffu, bi[n][lc], off);
                    if (ov > bv[n][lc] || (ov == bv[n][lc] && oi < bi[n][lc])) {
                        bv[n][lc] = ov; bi[n][lc] = oi;
                    }
                }
        if (lane < 4) {
#pragma unroll
            for (int n = 0; n < 8; n++)
#pragma unroll
                for (int lc = 0; lc < 2; lc++) {
                    int pos = 8 * n + 2 * tig + lc;
                    sRv[w * 64 + pos] = bv[n][lc];
                    sRi[w * 64 + pos] = bi[n][lc];
                }
        }
    }
    __syncthreads();   // (5) argmax partials visible

    if (t < 64) {
        // cross-warp reduce (ascending warp order -> first occurrence on ties)
        float bvv = sRv[t];
        int bii = sRi[t];
#pragma unroll
        for (int r = 1; r < 4; r++) {
            float v = sRv[r * 64 + t];
            if (v > bvv) { bvv = v; bii = sRi[r * 64 + t]; }
        }
        sInd[t] = bii;
    } else {
        // mask channel: dot(y2[:,p], wm) + bm, 4 partial chains
        int p = t - 64;
        float m0 = g_bm, m1 = 0.0f, m2 = 0.0f, m3 = 0.0f;
#pragma unroll 8
        for (int k = 0; k < 128; k += 4) {
            m0 = fmaf(sY[(k + 0) * 72 + p], g_wm[k + 0], m0);
            m1 = fmaf(sY[(k + 1) * 72 + p], g_wm[k + 1], m1);
            m2 = fmaf(sY[(k + 2) * 72 + p], g_wm[k + 2], m2);
            m3 = fmaf(sY[(k + 3) * 72 + p], g_wm[k + 3], m3);
        }
        out[NPOS + bb * 8192 + w0 + p] = lrelu((m0 + m1) + (m2 + m3));
    }
    __syncthreads();   // (6) sInd visible

    // ---- MoE regression: 4 warps x 16 positions ----
#pragma unroll 1
    for (int pi = 0; pi < 16; pi++) {
        int pos = w * 16 + pi;
        int ind = sInd[pos];
        const float4* W4 = g_moe4 + ind * 1024 + lane;
        const float4* X4 = (const float4*)(sXR + pos * 132);
        float h[4] = {0.0f, 0.0f, 0.0f, 0.0f};
#pragma unroll
        for (int blk = 0; blk < 4; blk++) {
            float4 wv[8];
#pragma unroll
            for (int u = 0; u < 8; u++)
                wv[u] = __ldg(W4 + (blk * 8 + u) * 32);
            float4 x[8];
#pragma unroll
            for (int u = 0; u < 8; u++)
                x[u] = X4[blk * 8 + u];
#pragma unroll
            for (int u = 0; u < 8; u++) {
                float s = h[u & 3];
                s = fmaf(x[u].x, wv[u].x, s);
                s = fmaf(x[u].y, wv[u].y, s);
                s = fmaf(x[u].z, wv[u].z, s);
                s = fmaf(x[u].w, wv[u].w, s);
                h[u & 3] = s;
            }
        }
        float hs = lrelu((h[0] + h[1]) + (h[2] + h[3]) + __ldg(cm2_b + ind * 32 + lane));
        float r = hs * __ldg(cm3_w + ind * 32 + lane);
#pragma unroll
        for (int off = 16; off; off >>= 1)
            r += __shfl_down_sync(0xffffffffu, r, off);
        if (lane == 0)
            out[bb * 8192 + w0 + pos] =
                ((float)ind + r + __ldg(cm3_b + ind)) * (1.0f / 128.0f);
    }
}

// ---------------- launch ----------------
extern "C" void kernel_launch(void* const* d_in, const int* in_sizes, int n_in,
                              void* d_out, int out_size)
{
    const float* x_in  = (const float*)d_in[0];
    const float* cl1_w = (const float*)d_in[1];
    const float* cl1_b = (const float*)d_in[2];
    const float* bn1_g = (const float*)d_in[3];
    const float* bn1_b = (const float*)d_in[4];
    const float* bn1_m = (const float*)d_in[5];
    const float* bn1_v = (const float*)d_in[6];
    const float* cl2_w = (const float*)d_in[7];
    const float* cl2_b = (const float*)d_in[8];
    const float* cl3_w = (const float*)d_in[9];
    const float* cl3_b = (const float*)d_in[10];
    const float* reg1_w = (const float*)d_in[11];
    const float* reg1_b = (const float*)d_in[12];
    const float* bnr_g = (const float*)d_in[13];
    const float* bnr_b = (const float*)d_in[14];
    const float* bnr_m = (const float*)d_in[15];
    const float* bnr_v = (const float*)d_in[16];
    const float* cm2_w = (const float*)d_in[17];
    const float* cm2_b = (const float*)d_in[18];
    const float* cm3_w = (const float*)d_in[19];
    const float* cm3_b = (const float*)d_in[20];
    float* out = (float*)d_out;

    const int SMEM_BYTES = 19008 * 4;   // 76032 B -> 3 CTAs/SM

    cudaFuncSetAttribute(fused_kernel, cudaFuncAttributeMaxDynamicSharedMemorySize,
                         SMEM_BYTES);

    prep_kernel<<<512, 256>>>(cl1_w, cl1_b, bn1_g, bn1_b, bn1_m, bn1_v,
                              cl2_w, cl2_b, cl3_w, cl3_b,
                              reg1_w, reg1_b, bnr_g, bnr_b, bnr_m, bnr_v,
                              cm2_w);

    fused_kernel<<<1024, 128, SMEM_BYTES>>>(x_in, cm2_b, cm3_w, cm3_b, out);
}

// round 14
// speedup vs baseline: 1.0277x; 1.0277x over previous
#include <cuda_runtime.h>
#include <cstdint>

#define SLOPE 0.01f
#define EPSBN 1e-5f
#define NPOS  65536
#define SPAD  64      // scalar-path activation tile stride
#define TPAD  132     // xr row stride (scalar path MoE)

// ---------------- device scratch ----------------
__device__ float g_w1t[16384];   // scalar path: [k][o] transposed, BN-folded
__device__ float g_w2t[16384];
__device__ float g_w3t[16384];
__device__ float g_wrt[16384];
__device__ uint32_t g_wA[4][3][16384];  // mma path: A-fragment tables (tf32 splits)
__device__ float g_b1[128], g_br[128], g_b2[128], g_b3[128], g_wm[128];
__device__ float g_bm;
__device__ float4 g_moe4[131072];       // [expert][c/4][lane]

__device__ __forceinline__ float lrelu(float v) { return v >= 0.0f ? v : SLOPE * v; }

// packed f32x2 helpers (FFMA2 path)
__device__ __forceinline__ unsigned long long pk2(float x) {
    unsigned long long r;
    asm("mov.b64 %0, {%1, %1};" : "=l"(r) : "f"(x));
    return r;
}
__device__ __forceinline__ void fma2(unsigned long long& d,
                                     unsigned long long a, unsigned long long b) {
    asm("fma.rn.f32x2 %0, %1, %2, %0;" : "+l"(d) : "l"(a), "l"(b));
}
__device__ __forceinline__ float2 up2(unsigned long long v) {
    float2 r;
    asm("mov.b64 {%0, %1}, %2;" : "=f"(r.x), "=f"(r.y) : "l"(v));
    return r;
}
__device__ __forceinline__ uint32_t tf32_of(float x) {
    uint32_t r;
    asm("cvt.rna.tf32.f32 %0, %1;" : "=r"(r) : "f"(x));
    return r;
}
__device__ __forceinline__ void mma8(float* c, const uint4 a, uint32_t b0, uint32_t b1) {
    asm volatile(
        "mma.sync.aligned.m16n8k8.row.col.f32.tf32.tf32.f32 "
        "{%0,%1,%2,%3}, {%4,%5,%6,%7}, {%8,%9}, {%0,%1,%2,%3};"
        : "+f"(c[0]), "+f"(c[1]), "+f"(c[2]), "+f"(c[3])
        : "r"(a.x), "r"(a.y), "r"(a.z), "r"(a.w), "r"(b0), "r"(b1));
}

// ---------------- merged prep ----------------
__global__ void prep_kernel(const float* __restrict__ cl1_w, const float* __restrict__ cl1_b,
                            const float* __restrict__ g1,    const float* __restrict__ be1,
                            const float* __restrict__ m1,    const float* __restrict__ v1,
                            const float* __restrict__ cl2_w, const float* __restrict__ cl2_b,
                            const float* __restrict__ cl3_w, const float* __restrict__ cl3_b,
                            const float* __restrict__ reg1_w,const float* __restrict__ reg1_b,
                            const float* __restrict__ gr,    const float* __restrict__ ber,
                            const float* __restrict__ mr,    const float* __restrict__ vr,
                            const float* __restrict__ cm2_w)
{
    int tid = blockIdx.x * blockDim.x + threadIdx.x;   // 0..131071

    // MoE repack
    {
        int e  = tid >> 10;
        int cg = (tid >> 5) & 31;
        int j  = tid & 31;
        const float* src = cm2_w + e * 4096 + (cg * 4) * 32 + j;
        g_moe4[tid] = make_float4(src[0], src[32], src[64], src[96]);
    }

    if (tid < 65536) {
        int l = tid >> 14, o = (tid >> 7) & 127, k = tid & 127;
        float wv;
        if (l == 0)      wv = cl1_w[o * 128 + k] * (g1[o] * rsqrtf(v1[o] + EPSBN));
        else if (l == 1) wv = reg1_w[o * 128 + k] * (gr[o] * rsqrtf(vr[o] + EPSBN));
        else if (l == 2) wv = cl2_w[o * 128 + k];
        else             wv = cl3_w[o * 128 + k];

        // scalar-path transposed tables
        if (l == 0)      g_w1t[k * 128 + o] = wv;
        else if (l == 1) g_wrt[k * 128 + o] = wv;
        else if (l == 2) g_w2t[k * 128 + o] = wv;
        else             g_w3t[k * 128 + o] = wv;

        // mma-path 3-way tf32 split fragments (m16n8k8 A layout)
        uint32_t sh = tf32_of(wv);
        float r1v = wv - __uint_as_float(sh);
        uint32_t smid = tf32_of(r1v);
        uint32_t sl = tf32_of(r1v - __uint_as_float(smid));
        int mtg = o >> 4;
        int g   = o & 7, h = (o >> 3) & 1;
        int kc  = k >> 3, tig = k & 3, kh = (k >> 2) & 1;
        int lane = g * 4 + tig, reg = h + 2 * kh;
        int fi = (kc * 8 + mtg) * 128 + lane * 4 + reg;
        g_wA[l][0][fi] = sh;
        g_wA[l][1][fi] = smid;
        g_wA[l][2][fi] = sl;
    }
    if (tid < 128) {
        float s = g1[tid] * rsqrtf(v1[tid] + EPSBN);
        g_b1[tid] = cl1_b[tid] * s + be1[tid] - m1[tid] * s;
        float s2 = gr[tid] * rsqrtf(vr[tid] + EPSBN);
        g_br[tid] = reg1_b[tid] * s2 + ber[tid] - mr[tid] * s2;
        g_b2[tid] = cl2_b[tid];
        g_b3[tid] = cl3_b[tid];
        g_wm[tid] = cl3_w[128 * 128 + tid];
        if (tid == 0) g_bm = cl3_b[128];
    }
}

// ================= scalar path (R9, verbatim) =================
__device__ __forceinline__ void gemm_tile_s(const float* __restrict__ wT,
                                            const float* sIn, float* sWb,
                                            float f[8][8])
{
    const int t    = threadIdx.x;
    const int warp = t >> 5, lane = t & 31;
    const int ty   = t >> 3, tx = t & 7;
    const int tyl  = ty & 3;
    const int lk   = lane >> 3, lc = lane & 7;
    const float4* wg  = (const float4*)wT;
    float*  sW  = sWb + warp * 512;
    float4* ws4 = (float4*)sW;

    unsigned long long acc[4][8];
#pragma unroll
    for (int i = 0; i < 4; i++)
#pragma unroll
        for (int j = 0; j < 8; j++) acc[i][j] = 0ull;

    float4 p[4];
#pragma unroll
    for (int j = 0; j < 4; j++)
        p[j] = wg[(lk + 4 * j) * 32 + warp * 8 + lc];

#pragma unroll 1
    for (int kk = 0; kk < 8; kk++) {
#pragma unroll
        for (int j = 0; j < 4; j++)
            ws4[(lk + 4 * j) * 8 + lc] = p[j];
        __syncwarp();
        if (kk < 7) {
#pragma unroll
            for (int j = 0; j < 4; j++)
                p[j] = wg[((kk + 1) * 16 + lk + 4 * j) * 32 + warp * 8 + lc];
        }
        const float* inb = sIn + kk * 16 * SPAD;
#pragma unroll
        for (int k = 0; k < 16; k++) {
            ulonglong2 a01 = *(const ulonglong2*)(sW + k * 32 + tyl * 8);
            ulonglong2 a23 = *(const ulonglong2*)(sW + k * 32 + tyl * 8 + 4);
            float4 xlo = *(const float4*)(inb + k * SPAD + tx * 4);
            float4 xhi = *(const float4*)(inb + k * SPAD + 32 + tx * 4);
            unsigned long long b[8];
            b[0] = pk2(xlo.x); b[1] = pk2(xlo.y); b[2] = pk2(xlo.z); b[3] = pk2(xlo.w);
            b[4] = pk2(xhi.x); b[5] = pk2(xhi.y); b[6] = pk2(xhi.z); b[7] = pk2(xhi.w);
#pragma unroll
            for (int j = 0; j < 8; j++) {
                fma2(acc[0][j], a01.x, b[j]);
                fma2(acc[1][j], a01.y, b[j]);
                fma2(acc[2][j], a23.x, b[j]);
                fma2(acc[3][j], a23.y, b[j]);
            }
        }
        __syncwarp();
    }

#pragma unroll
    for (int ip = 0; ip < 4; ip++)
#pragma unroll
        for (int j = 0; j < 8; j++) {
            float2 u = up2(acc[ip][j]);
            f[2 * ip][j]     = u.x;
            f[2 * ip + 1][j] = u.y;
        }
}

__device__ __forceinline__ void store_act_s(float* dst, const float* bias,
                                            float f[8][8], int ty, int tx)
{
#pragma unroll
    for (int i = 0; i < 8; i++) {
        float bi = bias[ty * 8 + i];
#pragma unroll
        for (int j = 0; j < 8; j++) f[i][j] = lrelu(f[i][j] + bi);
        *(float4*)(dst + (ty * 8 + i) * SPAD + tx * 4) =
            make_float4(f[i][0], f[i][1], f[i][2], f[i][3]);
        *(float4*)(dst + (ty * 8 + i) * SPAD + 32 + tx * 4) =
            make_float4(f[i][4], f[i][5], f[i][6], f[i][7]);
    }
}

__device__ void scalar_path(float* sm, const float* __restrict__ x_in,
                            const float* __restrict__ cm2_b,
                            const float* __restrict__ cm3_w,
                            const float* __restrict__ cm3_b,
                            float* __restrict__ out, int bb, int w0)
{
    float* sA   = sm;                      // x tile [128][64] (8192 < 8448)
    float* sAT  = sm;                      // xr tile [64][TPAD]
    float* sB   = sm + 8448;               // 128*64
    float* sW   = sB + 8192;               // 4x512 staging
    float* sRv  = sW;
    int*   sRi  = (int*)(sW + 1024);
    int*   sInd = (int*)(sW + 2048);

    const int t  = threadIdx.x;
    const int ty = t >> 3, tx = t & 7;
    const float* xb = x_in + (size_t)bb * 128 * 8192 + w0;

#pragma unroll
    for (int j = 0; j < 16; j++) {
        int idx = t + j * 128;
        int c = idx >> 4, p4 = idx & 15;
        float4 v = *(const float4*)(xb + c * 8192 + p4 * 4);
        *(float4*)(sA + c * SPAD + p4 * 4) = v;
    }
    __syncthreads();

    float f[8][8];

    gemm_tile_s(g_w1t, sA, sW, f);
    store_act_s(sB, g_b1, f, ty, tx);

    gemm_tile_s(g_wrt, sA, sW, f);
    __syncthreads();
#pragma unroll
    for (int i = 0; i < 8; i++) {
        float bi = g_br[ty * 8 + i];
#pragma unroll
        for (int j = 0; j < 8; j++) f[i][j] = lrelu(f[i][j] + bi);
    }
#pragma unroll
    for (int j = 0; j < 8; j++) {
        int pos = (j < 4) ? (tx * 4 + j) : (32 + tx * 4 + j - 4);
#pragma unroll
        for (int ip = 0; ip < 4; ip++)
            *(float2*)(sAT + pos * TPAD + ty * 8 + 2 * ip) =
                make_float2(f[2 * ip][j], f[2 * ip + 1][j]);
    }
    __syncthreads();

    gemm_tile_s(g_w2t, sB, sW, f);
    __syncthreads();
    store_act_s(sB, g_b2, f, ty, tx);
    __syncthreads();

    gemm_tile_s(g_w3t, sB, sW, f);
    __syncthreads();

#pragma unroll
    for (int j = 0; j < 8; j++) {
        int pos = (j < 4) ? (tx * 4 + j) : (32 + tx * 4 + j - 4);
        float bv = f[0][j] + g_b3[ty * 8];
        int bi = 0;
#pragma unroll
        for (int i = 1; i < 8; i++) {
            float v = f[i][j] + g_b3[ty * 8 + i];
            if (v > bv) { bv = v; bi = i; }
        }
        sRv[ty * 64 + pos] = bv;
        sRi[ty * 64 + pos] = ty * 8 + bi;
    }
    __syncthreads();

    if (t < 64) {
        float bv = sRv[t];
        int bi = sRi[t];
#pragma unroll
        for (int r = 1; r < 16; r++) {
            float v = sRv[r * 64 + t];
            if (v > bv) { bv = v; bi = sRi[r * 64 + t]; }
        }
        sInd[t] = bi;
    } else {
        int p = t - 64;
        float m0 = g_bm, m1 = 0.0f, m2 = 0.0f, m3 = 0.0f;
#pragma unroll 8
        for (int k = 0; k < 128; k += 4) {
            m0 = fmaf(sB[(k + 0) * SPAD + p], g_wm[k + 0], m0);
            m1 = fmaf(sB[(k + 1) * SPAD + p], g_wm[k + 1], m1);
            m2 = fmaf(sB[(k + 2) * SPAD + p], g_wm[k + 2], m2);
            m3 = fmaf(sB[(k + 3) * SPAD + p], g_wm[k + 3], m3);
        }
        out[NPOS + bb * 8192 + w0 + p] = lrelu((m0 + m1) + (m2 + m3));
    }
    __syncthreads();

    const int warp = t >> 5, lane = t & 31;
#pragma unroll 1
    for (int pi = 0; pi < 16; pi++) {
        int pos = warp * 16 + pi;
        int ind = sInd[pos];
        const float4* W4 = g_moe4 + ind * 1024 + lane;
        const float4* X4 = (const float4*)(sAT + pos * TPAD);
        float h[4] = {0.0f, 0.0f, 0.0f, 0.0f};
#pragma unroll
        for (int blk = 0; blk < 4; blk++) {
            float4 w[8];
#pragma unroll
            for (int u = 0; u < 8; u++)
                w[u] = __ldg(W4 + (blk * 8 + u) * 32);
            float4 x[8];
#pragma unroll
            for (int u = 0; u < 8; u++)
                x[u] = X4[blk * 8 + u];
#pragma unroll
            for (int u = 0; u < 8; u++) {
                float s = h[u & 3];
                s = fmaf(x[u].x, w[u].x, s);
                s = fmaf(x[u].y, w[u].y, s);
                s = fmaf(x[u].z, w[u].z, s);
                s = fmaf(x[u].w, w[u].w, s);
                h[u & 3] = s;
            }
        }
        float hs = lrelu((h[0] + h[1]) + (h[2] + h[3]) + __ldg(cm2_b + ind * 32 + lane));
        float r = hs * __ldg(cm3_w + ind * 32 + lane);
#pragma unroll
        for (int off = 16; off; off >>= 1)
            r += __shfl_down_sync(0xffffffffu, r, off);
        if (lane == 0)
            out[bb * 8192 + w0 + pos] =
                ((float)ind + r + __ldg(cm3_b + ind)) * (1.0f / 128.0f);
    }
}

// ================= mma path (R13, argmax scratch relocated) =================
template<int NS>
__device__ __forceinline__ void gemm_mma(const uint4* __restrict__ A0,
                                         const uint4* __restrict__ A1,
                                         const uint4* __restrict__ A2,
                                         const float* __restrict__ sIn,
                                         float acc[2][8][4], int w, int lane)
{
    const int g = lane >> 2, tig = lane & 3;
#pragma unroll
    for (int mt = 0; mt < 2; mt++)
#pragma unroll
        for (int n = 0; n < 8; n++)
#pragma unroll
            for (int c = 0; c < 4; c++) acc[mt][n][c] = 0.0f;

    uint4 Ab[2][2][NS];
    {
        int fo = (2 * w) * 32 + lane;
#pragma unroll
        for (int mt = 0; mt < 2; mt++) {
            Ab[0][mt][0] = __ldg(A0 + fo + mt * 32);
            if (NS > 1) {
                Ab[0][mt][1] = __ldg(A1 + fo + mt * 32);
                Ab[0][mt][2] = __ldg(A2 + fo + mt * 32);
            }
        }
    }

#pragma unroll 1
    for (int kc = 0; kc < 16; kc++) {
        int cur = kc & 1;
        if (kc < 15) {
            int fo = ((kc + 1) * 8 + 2 * w) * 32 + lane;
#pragma unroll
            for (int mt = 0; mt < 2; mt++) {
                Ab[cur ^ 1][mt][0] = __ldg(A0 + fo + mt * 32);
                if (NS > 1) {
                    Ab[cur ^ 1][mt][1] = __ldg(A1 + fo + mt * 32);
                    Ab[cur ^ 1][mt][2] = __ldg(A2 + fo + mt * 32);
                }
            }
        }
        const float* bp = sIn + (kc * 8 + tig) * 72 + g;
#pragma unroll
        for (int n = 0; n < 8; n++) {
            float x0 = bp[8 * n], x1 = bp[288 + 8 * n];
            uint32_t h0 = tf32_of(x0), h1 = tf32_of(x1);
            if (NS == 1) {
#pragma unroll
                for (int mt = 0; mt < 2; mt++)
                    mma8(acc[mt][n], Ab[cur][mt][0], h0, h1);
            } else {
                float r0 = x0 - __uint_as_float(h0), r1 = x1 - __uint_as_float(h1);
                uint32_t m0 = tf32_of(r0), m1 = tf32_of(r1);
                uint32_t l0 = tf32_of(r0 - __uint_as_float(m0));
                uint32_t l1 = tf32_of(r1 - __uint_as_float(m1));
#pragma unroll
                for (int mt = 0; mt < 2; mt++) {
                    mma8(acc[mt][n], Ab[cur][mt][0], h0, h1);
                    mma8(acc[mt][n], Ab[cur][mt][0], m0, m1);
                    mma8(acc[mt][n], Ab[cur][mt][1], h0, h1);
                    mma8(acc[mt][n], Ab[cur][mt][0], l0, l1);
                    mma8(acc[mt][n], Ab[cur][mt][2], h0, h1);
                    mma8(acc[mt][n], Ab[cur][mt][1], m0, m1);
                }
            }
        }
    }
}

__device__ __forceinline__ void epi_storeY(float* sY, const float* bias,
                                           float acc[2][8][4], int w, int lane)
{
    const int g = lane >> 2, tig = lane & 3;
#pragma unroll
    for (int mt = 0; mt < 2; mt++)
#pragma unroll
        for (int h = 0; h < 2; h++) {
            int ch = 32 * w + 16 * mt + g + 8 * h;
            float bi = bias[ch];
#pragma unroll
            for (int n = 0; n < 8; n++) {
                float v0 = lrelu(acc[mt][n][2 * h]     + bi);
                float v1 = lrelu(acc[mt][n][2 * h + 1] + bi);
                *(float2*)(sY + ch * 72 + 8 * n + 2 * tig) = make_float2(v0, v1);
            }
        }
}

__device__ void mma_path(float* sm, const float* __restrict__ x_in,
                         const float* __restrict__ cm2_b,
                         const float* __restrict__ cm3_w,
                         const float* __restrict__ cm3_b,
                         float* __restrict__ out, int bb, int w0)
{
    float* sX   = sm;                 // [128][72] fp32 (9216 floats)
    float* sXR  = sm;                 // [64][132] xr (8448, aliases sX after R1)
    float* sY   = sm + 9216;          // [128][72]
    float* sRv  = sm + 8448;          // 4*64 (in dead sX tail region)
    int*   sRi  = (int*)(sm + 8704);
    int*   sInd = (int*)(sm + 8960);

    const int t = threadIdx.x, w = t >> 5, lane = t & 31;
    const int g = lane >> 2, tig = lane & 3;
    const float* xb = x_in + (size_t)bb * 128 * 8192 + w0;

#pragma unroll
    for (int j = 0; j < 16; j++) {
        int idx = t + j * 128;
        int c = idx >> 4, p4 = idx & 15;
        float4 v = *(const float4*)(xb + c * 8192 + p4 * 4);
        *(float4*)(sX + c * 72 + p4 * 4) = v;
    }
    __syncthreads();

    float acc[2][8][4];
    const uint4 *A0, *A1, *A2;

    A0 = (const uint4*)g_wA[0][0]; A1 = (const uint4*)g_wA[0][1]; A2 = (const uint4*)g_wA[0][2];
    gemm_mma<3>(A0, A1, A2, sX, acc, w, lane);
    epi_storeY(sY, g_b1, acc, w, lane);

    A0 = (const uint4*)g_wA[1][0];
    gemm_mma<1>(A0, A0, A0, sX, acc, w, lane);
    __syncthreads();
#pragma unroll
    for (int mt = 0; mt < 2; mt++)
#pragma unroll
        for (int h = 0; h < 2; h++) {
            int ch = 32 * w + 16 * mt + g + 8 * h;
            float bi = g_br[ch];
#pragma unroll
            for (int n = 0; n < 8; n++) {
                int pos = 8 * n + 2 * tig;
                sXR[pos * 132 + ch]       = lrelu(acc[mt][n][2 * h]     + bi);
                sXR[(pos + 1) * 132 + ch] = lrelu(acc[mt][n][2 * h + 1] + bi);
            }
        }

    A0 = (const uint4*)g_wA[2][0]; A1 = (const uint4*)g_wA[2][1]; A2 = (const uint4*)g_wA[2][2];
    gemm_mma<3>(A0, A1, A2, sY, acc, w, lane);
    __syncthreads();
    epi_storeY(sY, g_b2, acc, w, lane);
    __syncthreads();

    A0 = (const uint4*)g_wA[3][0]; A1 = (const uint4*)g_wA[3][1]; A2 = (const uint4*)g_wA[3][2];
    gemm_mma<3>(A0, A1, A2, sY, acc, w, lane);

    {
        float bv[8][2];
        int   bi[8][2];
#pragma unroll
        for (int n = 0; n < 8; n++)
#pragma unroll
            for (int lc = 0; lc < 2; lc++) {
                float best = acc[0][n][lc] + g_b3[32 * w + g];
                int   bidx = 32 * w + g;
#pragma unroll
                for (int cand = 1; cand < 4; cand++) {
                    int mt = cand >> 1, h = cand & 1;
                    int ch = 32 * w + 16 * mt + g + 8 * h;
                    float v = acc[mt][n][2 * h + lc] + g_b3[ch];
                    if (v > best) { best = v; bidx = ch; }
                }
                bv[n][lc] = best; bi[n][lc] = bidx;
            }
#pragma unroll
        for (int off = 4; off <= 16; off <<= 1)
#pragma unroll
            for (int n = 0; n < 8; n++)
#pragma unroll
                for (int lc = 0; lc < 2; lc++) {
                    float ov = __shfl_xor_sync(0xffffffffu, bv[n][lc], off);
                    int   oi = __shfl_xor_sync(0xffffffffu, bi[n][lc], off);
                    if (ov > bv[n][lc] || (ov == bv[n][lc] && oi < bi[n][lc])) {
                        bv[n][lc] = ov; bi[n][lc] = oi;
                    }
                }
        if (lane < 4) {
#pragma unroll
            for (int n = 0; n < 8; n++)
#pragma unroll
                for (int lc = 0; lc < 2; lc++) {
                    int pos = 8 * n + 2 * tig + lc;
                    sRv[w * 64 + pos] = bv[n][lc];
                    sRi[w * 64 + pos] = bi[n][lc];
                }
        }
    }
    __syncthreads();

    if (t < 64) {
        float bvv = sRv[t];
        int bii = sRi[t];
#pragma unroll
        for (int r = 1; r < 4; r++) {
            float v = sRv[r * 64 + t];
            if (v > bvv) { bvv = v; bii = sRi[r * 64 + t]; }
        }
        sInd[t] = bii;
    } else {
        int p = t - 64;
        float m0 = g_bm, m1 = 0.0f, m2 = 0.0f, m3 = 0.0f;
#pragma unroll 8
        for (int k = 0; k < 128; k += 4) {
            m0 = fmaf(sY[(k + 0) * 72 + p], g_wm[k + 0], m0);
            m1 = fmaf(sY[(k + 1) * 72 + p], g_wm[k + 1], m1);
            m2 = fmaf(sY[(k + 2) * 72 + p], g_wm[k + 2], m2);
            m3 = fmaf(sY[(k + 3) * 72 + p], g_wm[k + 3], m3);
        }
        out[NPOS + bb * 8192 + w0 + p] = lrelu((m0 + m1) + (m2 + m3));
    }
    __syncthreads();

#pragma unroll 1
    for (int pi = 0; pi < 16; pi++) {
        int pos = w * 16 + pi;
        int ind = sInd[pos];
        const float4* W4 = g_moe4 + ind * 1024 + lane;
        const float4* X4 = (const float4*)(sXR + pos * 132);
        float h[4] = {0.0f, 0.0f, 0.0f, 0.0f};
#pragma unroll
        for (int blk = 0; blk < 4; blk++) {
            float4 wv[8];
#pragma unroll
            for (int u = 0; u < 8; u++)
                wv[u] = __ldg(W4 + (blk * 8 + u) * 32);
            float4 x[8];
#pragma unroll
            for (int u = 0; u < 8; u++)
                x[u] = X4[blk * 8 + u];
#pragma unroll
            for (int u = 0; u < 8; u++) {
                float s = h[u & 3];
                s = fmaf(x[u].x, wv[u].x, s);
                s = fmaf(x[u].y, wv[u].y, s);
                s = fmaf(x[u].z, wv[u].z, s);
                s = fmaf(x[u].w, wv[u].w, s);
                h[u & 3] = s;
            }
        }
        float hs = lrelu((h[0] + h[1]) + (h[2] + h[3]) + __ldg(cm2_b + ind * 32 + lane));
        float r = hs * __ldg(cm3_w + ind * 32 + lane);
#pragma unroll
        for (int off = 16; off; off >>= 1)
            r += __shfl_down_sync(0xffffffffu, r, off);
        if (lane == 0)
            out[bb * 8192 + w0 + pos] =
                ((float)ind + r + __ldg(cm3_b + ind)) * (1.0f / 128.0f);
    }
}

// ================= dispatcher =================
__global__ void __launch_bounds__(128, 3)
fused_kernel(const float* __restrict__ x_in,
             const float* __restrict__ cm2_b,
             const float* __restrict__ cm3_w, const float* __restrict__ cm3_b,
             float* __restrict__ out)
{
    extern __shared__ float sm[];
    const int bb = blockIdx.x >> 7;
    const int w0 = (blockIdx.x & 127) * 64;
    if ((blockIdx.x % 7) < 3)
        mma_path(sm, x_in, cm2_b, cm3_w, cm3_b, out, bb, w0);
    else
        scalar_path(sm, x_in, cm2_b, cm3_w, cm3_b, out, bb, w0);
}

// ---------------- launch ----------------
extern "C" void kernel_launch(void* const* d_in, const int* in_sizes, int n_in,
                              void* d_out, int out_size)
{
    const float* x_in  = (const float*)d_in[0];
    const float* cl1_w = (const float*)d_in[1];
    const float* cl1_b = (const float*)d_in[2];
    const float* bn1_g = (const float*)d_in[3];
    const float* bn1_b = (const float*)d_in[4];
    const float* bn1_m = (const float*)d_in[5];
    const float* bn1_v = (const float*)d_in[6];
    const float* cl2_w = (const float*)d_in[7];
    const float* cl2_b = (const float*)d_in[8];
    const float* cl3_w = (const float*)d_in[9];
    const float* cl3_b = (const float*)d_in[10];
    const float* reg1_w = (const float*)d_in[11];
    const float* reg1_b = (const float*)d_in[12];
    const float* bnr_g = (const float*)d_in[13];
    const float* bnr_b = (const float*)d_in[14];
    const float* bnr_m = (const float*)d_in[15];
    const float* bnr_v = (const float*)d_in[16];
    const float* cm2_w = (const float*)d_in[17];
    const float* cm2_b = (const float*)d_in[18];
    const float* cm3_w = (const float*)d_in[19];
    const float* cm3_b = (const float*)d_in[20];
    float* out = (float*)d_out;

    const int SMEM_BYTES = 18752 * 4;   // 75008 B -> 3 CTAs/SM

    cudaFuncSetAttribute(fused_kernel, cudaFuncAttributeMaxDynamicSharedMemorySize,
                         SMEM_BYTES);

    prep_kernel<<<512, 256>>>(cl1_w, cl1_b, bn1_g, bn1_b, bn1_m, bn1_v,
                              cl2_w, cl2_b, cl3_w, cl3_b,
                              reg1_w, reg1_b, bnr_g, bnr_b, bnr_m, bnr_v,
                              cm2_w);

    fused_kernel<<<1024, 128, SMEM_BYTES>>>(x_in, cm2_b, cm3_w, cm3_b, out);
}

// round 15
// speedup vs baseline: 1.4305x; 1.3920x over previous
#include <cuda_runtime.h>
#include <cstdint>

#define SLOPE 0.01f
#define EPSBN 1e-5f
#define NPOS  65536
#define XS    72      // sA stride (x tile): %4==0 and ==8 mod 32 -> mma B conflict-free
#define YS    64      // sB stride (y tiles, scalar-only)
#define TPAD  132     // xr row stride

// ---------------- device scratch ----------------
__device__ float g_w1t[16384];   // [k][o] transposed, BN-folded (scalar)
__device__ float g_w2t[16384];
__device__ float g_w3t[16384];
__device__ uint32_t g_wA1[16384]; // reg1 tf32-hi A-fragments (m16n8k8 layout)
__device__ float g_b1[128], g_br[128], g_b2[128], g_b3[128], g_wm[128];
__device__ float g_bm;
__device__ float4 g_moe4[131072];

__device__ __forceinline__ float lrelu(float v) { return v >= 0.0f ? v : SLOPE * v; }

__device__ __forceinline__ unsigned long long pk2(float x) {
    unsigned long long r;
    asm("mov.b64 %0, {%1, %1};" : "=l"(r) : "f"(x));
    return r;
}
__device__ __forceinline__ void fma2(unsigned long long& d,
                                     unsigned long long a, unsigned long long b) {
    asm("fma.rn.f32x2 %0, %1, %2, %0;" : "+l"(d) : "l"(a), "l"(b));
}
__device__ __forceinline__ float2 up2(unsigned long long v) {
    float2 r;
    asm("mov.b64 {%0, %1}, %2;" : "=f"(r.x), "=f"(r.y) : "l"(v));
    return r;
}
__device__ __forceinline__ uint32_t tf32_of(float x) {
    uint32_t r;
    asm("cvt.rna.tf32.f32 %0, %1;" : "=r"(r) : "f"(x));
    return r;
}
__device__ __forceinline__ void mma8(float* c, const uint4 a, uint32_t b0, uint32_t b1) {
    asm volatile(
        "mma.sync.aligned.m16n8k8.row.col.f32.tf32.tf32.f32 "
        "{%0,%1,%2,%3}, {%4,%5,%6,%7}, {%8,%9}, {%0,%1,%2,%3};"
        : "+f"(c[0]), "+f"(c[1]), "+f"(c[2]), "+f"(c[3])
        : "r"(a.x), "r"(a.y), "r"(a.z), "r"(a.w), "r"(b0), "r"(b1));
}

// ---------------- prep ----------------
__global__ void prep_kernel(const float* __restrict__ cl1_w, const float* __restrict__ cl1_b,
                            const float* __restrict__ g1,    const float* __restrict__ be1,
                            const float* __restrict__ m1,    const float* __restrict__ v1,
                            const float* __restrict__ cl2_w, const float* __restrict__ cl2_b,
                            const float* __restrict__ cl3_w, const float* __restrict__ cl3_b,
                            const float* __restrict__ reg1_w,const float* __restrict__ reg1_b,
                            const float* __restrict__ gr,    const float* __restrict__ ber,
                            const float* __restrict__ mr,    const float* __restrict__ vr,
                            const float* __restrict__ cm2_w)
{
    int tid = blockIdx.x * blockDim.x + threadIdx.x;   // 0..131071

    {   // MoE repack
        int e  = tid >> 10;
        int cg = (tid >> 5) & 31;
        int j  = tid & 31;
        const float* src = cm2_w + e * 4096 + (cg * 4) * 32 + j;
        g_moe4[tid] = make_float4(src[0], src[32], src[64], src[96]);
    }

    if (tid < 65536) {
        int l = tid >> 14, o = (tid >> 7) & 127, k = tid & 127;
        if (l == 0) {
            float wv = cl1_w[o * 128 + k] * (g1[o] * rsqrtf(v1[o] + EPSBN));
            g_w1t[k * 128 + o] = wv;
        } else if (l == 1) {
            float wv = reg1_w[o * 128 + k] * (gr[o] * rsqrtf(vr[o] + EPSBN));
            // m16n8k8 A-fragment slot (hi split only, NS1)
            int mtg = o >> 4;
            int g   = o & 7, h = (o >> 3) & 1;
            int kc  = k >> 3, tig = k & 3, kh = (k >> 2) & 1;
            int lane = g * 4 + tig, reg = h + 2 * kh;
            g_wA1[(kc * 8 + mtg) * 128 + lane * 4 + reg] = tf32_of(wv);
        } else if (l == 2) {
            g_w2t[k * 128 + o] = cl2_w[o * 128 + k];
        } else {
            g_w3t[k * 128 + o] = cl3_w[o * 128 + k];
        }
    }
    if (tid < 128) {
        float s = g1[tid] * rsqrtf(v1[tid] + EPSBN);
        g_b1[tid] = cl1_b[tid] * s + be1[tid] - m1[tid] * s;
        float s2 = gr[tid] * rsqrtf(vr[tid] + EPSBN);
        g_br[tid] = reg1_b[tid] * s2 + ber[tid] - mr[tid] * s2;
        g_b2[tid] = cl2_b[tid];
        g_b3[tid] = cl3_b[tid];
        g_wm[tid] = cl3_w[128 * 128 + tid];
        if (tid == 0) g_bm = cl3_b[128];
    }
}

// ---------------- scalar 128x128x64 GEMM (FFMA2), 8-row weight chunks ----------------
// Warp w: channels 32w..32w+31; thread tile 8ch x 8pos.
// sWb: 4 x 256 floats warp-private staging. IS = input row stride.
template<int IS>
__device__ __forceinline__ void gemm_tile_s(const float* __restrict__ wT,
                                            const float* sIn, float* sWb,
                                            float f[8][8])
{
    const int t    = threadIdx.x;
    const int warp = t >> 5, lane = t & 31;
    const int ty   = t >> 3, tx = t & 7;
    const int tyl  = ty & 3;
    const int lr   = lane >> 3, lc = lane & 7;
    const float4* wg  = (const float4*)wT;
    float*  sW  = sWb + warp * 256;         // [8 k][32 ch]
    float4* ws4 = (float4*)sW;

    unsigned long long acc[4][8];
#pragma unroll
    for (int i = 0; i < 4; i++)
#pragma unroll
        for (int j = 0; j < 8; j++) acc[i][j] = 0ull;

    // prefetch chunk 0: [8k][32ch] = 64 float4, 2/lane
    float4 p0 = wg[lr * 32 + warp * 8 + lc];
    float4 p1 = wg[(lr + 4) * 32 + warp * 8 + lc];

#pragma unroll 1
    for (int c8 = 0; c8 < 16; c8++) {
        ws4[lr * 8 + lc]       = p0;
        ws4[(lr + 4) * 8 + lc] = p1;
        __syncwarp();
        if (c8 < 15) {
            int base = (c8 + 1) * 8;
            p0 = wg[(base + lr) * 32 + warp * 8 + lc];
            p1 = wg[(base + lr + 4) * 32 + warp * 8 + lc];
        }
        const float* inb = sIn + c8 * 8 * IS;
#pragma unroll
        for (int k = 0; k < 8; k++) {
            ulonglong2 a01 = *(const ulonglong2*)(sW + k * 32 + tyl * 8);
            ulonglong2 a23 = *(const ulonglong2*)(sW + k * 32 + tyl * 8 + 4);
            float4 xlo = *(const float4*)(inb + k * IS + tx * 4);
            float4 xhi = *(const float4*)(inb + k * IS + 32 + tx * 4);
            unsigned long long b[8];
            b[0] = pk2(xlo.x); b[1] = pk2(xlo.y); b[2] = pk2(xlo.z); b[3] = pk2(xlo.w);
            b[4] = pk2(xhi.x); b[5] = pk2(xhi.y); b[6] = pk2(xhi.z); b[7] = pk2(xhi.w);
#pragma unroll
            for (int j = 0; j < 8; j++) {
                fma2(acc[0][j], a01.x, b[j]);
                fma2(acc[1][j], a01.y, b[j]);
                fma2(acc[2][j], a23.x, b[j]);
                fma2(acc[3][j], a23.y, b[j]);
            }
        }
        __syncwarp();
    }

#pragma unroll
    for (int ip = 0; ip < 4; ip++)
#pragma unroll
        for (int j = 0; j < 8; j++) {
            float2 u = up2(acc[ip][j]);
            f[2 * ip][j]     = u.x;
            f[2 * ip + 1][j] = u.y;
        }
}

__device__ __forceinline__ void store_act_s(float* dst, const float* bias,
                                            float f[8][8], int ty, int tx)
{
#pragma unroll
    for (int i = 0; i < 8; i++) {
        float bi = bias[ty * 8 + i];
#pragma unroll
        for (int j = 0; j < 8; j++) f[i][j] = lrelu(f[i][j] + bi);
        *(float4*)(dst + (ty * 8 + i) * YS + tx * 4) =
            make_float4(f[i][0], f[i][1], f[i][2], f[i][3]);
        *(float4*)(dst + (ty * 8 + i) * YS + 32 + tx * 4) =
            make_float4(f[i][4], f[i][5], f[i][6], f[i][7]);
    }
}

// ---------------- R1 via NS1 tf32 mma (R13-validated mapping) ----------------
// Warp w: channels 32w..+31 (mt 0..1), positions 0..63 (n 0..7).
__device__ __forceinline__ void gemm_r1(const float* __restrict__ sIn,
                                        float acc[2][8][4], int w, int lane)
{
    const uint4* A0 = (const uint4*)g_wA1;
    const int g = lane >> 2, tig = lane & 3;
#pragma unroll
    for (int mt = 0; mt < 2; mt++)
#pragma unroll
        for (int n = 0; n < 8; n++)
#pragma unroll
            for (int c = 0; c < 4; c++) acc[mt][n][c] = 0.0f;

    uint4 Ab[2][2];
    {
        int fo = (2 * w) * 32 + lane;
        Ab[0][0] = __ldg(A0 + fo);
        Ab[0][1] = __ldg(A0 + fo + 32);
    }
#pragma unroll 1
    for (int kc = 0; kc < 16; kc++) {
        int cur = kc & 1;
        if (kc < 15) {
            int fo = ((kc + 1) * 8 + 2 * w) * 32 + lane;
            Ab[cur ^ 1][0] = __ldg(A0 + fo);
            Ab[cur ^ 1][1] = __ldg(A0 + fo + 32);
        }
        const float* bp = sIn + (kc * 8 + tig) * XS + g;
#pragma unroll
        for (int n = 0; n < 8; n++) {
            float x0 = bp[8 * n], x1 = bp[4 * XS + 8 * n];
            uint32_t h0 = tf32_of(x0), h1 = tf32_of(x1);
            mma8(acc[0][n], Ab[cur][0], h0, h1);
            mma8(acc[1][n], Ab[cur][1], h0, h1);
        }
    }
}

// ---------------- fused main kernel (128 threads, 3 CTAs/SM) ----------------
__global__ void __launch_bounds__(128, 3)
fused_kernel(const float* __restrict__ x_in,
             const float* __restrict__ cm2_b,
             const float* __restrict__ cm3_w, const float* __restrict__ cm3_b,
             float* __restrict__ out)
{
    extern __shared__ float sm[];
    float* sA   = sm;                      // x tile [128][XS] (9216 floats)
    float* sXR  = sm;                      // xr [64][TPAD] (8448, aliases sA)
    int*   sInd = (int*)(sm + 8448);       // 64 (sA tail, free after R1)
    float* sB   = sm + 9216;               // y tile [128][YS] (8192)
    float* sW   = sB + 8192;               // 4 x 256 staging (1024)
    float* sRv  = sW;                      // alias after L3: 4*64 vals
    int*   sRi  = (int*)(sW + 256);        // 4*64 idx

    const int t = threadIdx.x, w = t >> 5, lane = t & 31;
    const int ty = t >> 3, tx = t & 7;
    const int g = lane >> 2, tig = lane & 3;
    const int bb = blockIdx.x >> 7;
    const int w0 = (blockIdx.x & 127) * 64;
    const float* xb = x_in + (size_t)bb * 128 * 8192 + w0;

    // stage x tile [ch][XS]
#pragma unroll
    for (int j = 0; j < 16; j++) {
        int idx = t + j * 128;
        int c = idx >> 4, p4 = idx & 15;
        float4 v = *(const float4*)(xb + c * 8192 + p4 * 4);
        *(float4*)(sA + c * XS + p4 * 4) = v;
    }
    __syncthreads();   // (1) x visible

    float f[8][8];

    // ---- L1 scalar: y1 = lrelu(bn(cl1 @ x)) : sA -> sB ----
    gemm_tile_s<XS>(g_w1t, sA, sW, f);
    store_act_s(sB, g_b1, f, ty, tx);

    // ---- R1 mma NS1: xr = lrelu(bn(reg1 @ x)) : sA -> sXR (transposed) ----
    {
        float acc[2][8][4];
        gemm_r1(sA, acc, w, lane);
        __syncthreads();   // (2) all sA reads done (L1 + R1); y1 stores visible
#pragma unroll
        for (int mt = 0; mt < 2; mt++)
#pragma unroll
            for (int h = 0; h < 2; h++) {
                int ch = 32 * w + 16 * mt + g + 8 * h;
                float bi = g_br[ch];
#pragma unroll
                for (int n = 0; n < 8; n++) {
                    int pos = 8 * n + 2 * tig;
                    sXR[pos * TPAD + ch]       = lrelu(acc[mt][n][2 * h]     + bi);
                    sXR[(pos + 1) * TPAD + ch] = lrelu(acc[mt][n][2 * h + 1] + bi);
                }
            }
    }

    // ---- L2 scalar: y2 = lrelu(cl2 @ y1) : sB -> sB ----
    gemm_tile_s<YS>(g_w2t, sB, sW, f);
    __syncthreads();   // (3) all reads of y1 done; sXR writes visible
    store_act_s(sB, g_b2, f, ty, tx);
    __syncthreads();   // (4) y2 complete

    // ---- L3 scalar: logits : sB -> regs ----
    gemm_tile_s<YS>(g_w3t, sB, sW, f);
    __syncthreads();   // (5) all warps done with sW staging -> argmax alias OK

    // per-thread argmax over 8 ch, then shfl-reduce over ty-groups in warp
    {
        float bv[8];
        int   bi[8];
#pragma unroll
        for (int j = 0; j < 8; j++) {
            float best = f[0][j] + g_b3[ty * 8];
            int bidx = ty * 8;
#pragma unroll
            for (int i = 1; i < 8; i++) {
                float v = f[i][j] + g_b3[ty * 8 + i];
                if (v > best) { best = v; bidx = ty * 8 + i; }
            }
            bv[j] = best; bi[j] = bidx;
        }
#pragma unroll
        for (int off = 8; off <= 16; off <<= 1)
#pragma unroll
            for (int j = 0; j < 8; j++) {
                float ov = __shfl_xor_sync(0xffffffffu, bv[j], off);
                int   oi = __shfl_xor_sync(0xffffffffu, bi[j], off);
                if (ov > bv[j] || (ov == bv[j] && oi < bi[j])) { bv[j] = ov; bi[j] = oi; }
            }
        if (lane < 8) {
#pragma unroll
            for (int j = 0; j < 8; j++) {
                int pos = (j < 4) ? (tx * 4 + j) : (32 + tx * 4 + j - 4);
                sRv[w * 64 + pos] = bv[j];
                sRi[w * 64 + pos] = bi[j];
            }
        }
    }
    __syncthreads();   // (6) argmax partials visible

    if (t < 64) {
        // reduce across 4 warps (ascending ch -> first occurrence kept)
        float bvv = sRv[t];
        int bii = sRi[t];
#pragma unroll
        for (int r = 1; r < 4; r++) {
            float v = sRv[r * 64 + t];
            if (v > bvv) { bvv = v; bii = sRi[r * 64 + t]; }
        }
        sInd[t] = bii;
    } else {
        // mask channel: dot(y2[:,p], wm) + bm, 4 partial chains
        int p = t - 64;
        float m0 = g_bm, m1 = 0.0f, m2 = 0.0f, m3 = 0.0f;
#pragma unroll 8
        for (int k = 0; k < 128; k += 4) {
            m0 = fmaf(sB[(k + 0) * YS + p], g_wm[k + 0], m0);
            m1 = fmaf(sB[(k + 1) * YS + p], g_wm[k + 1], m1);
            m2 = fmaf(sB[(k + 2) * YS + p], g_wm[k + 2], m2);
            m3 = fmaf(sB[(k + 3) * YS + p], g_wm[k + 3], m3);
        }
        out[NPOS + bb * 8192 + w0 + p] = lrelu((m0 + m1) + (m2 + m3));
    }
    __syncthreads();   // (7) sInd visible

    // ---- MoE regression: 4 warps x 16 positions ----
#pragma unroll 1
    for (int pi = 0; pi < 16; pi++) {
        int pos = w * 16 + pi;
        int ind = sInd[pos];
        const float4* W4 = g_moe4 + ind * 1024 + lane;
        const float4* X4 = (const float4*)(sXR + pos * TPAD);
        float h[4] = {0.0f, 0.0f, 0.0f, 0.0f};
#pragma unroll
        for (int blk = 0; blk < 4; blk++) {
            float4 wv[8];
#pragma unroll
            for (int u = 0; u < 8; u++)
                wv[u] = __ldg(W4 + (blk * 8 + u) * 32);
            float4 x[8];
#pragma unroll
            for (int u = 0; u < 8; u++)
                x[u] = X4[blk * 8 + u];
#pragma unroll
            for (int u = 0; u < 8; u++) {
                float s = h[u & 3];
                s = fmaf(x[u].x, wv[u].x, s);
                s = fmaf(x[u].y, wv[u].y, s);
                s = fmaf(x[u].z, wv[u].z, s);
                s = fmaf(x[u].w, wv[u].w, s);
                h[u & 3] = s;
            }
        }
        float hs = lrelu((h[0] + h[1]) + (h[2] + h[3]) + __ldg(cm2_b + ind * 32 + lane));
        float r = hs * __ldg(cm3_w + ind * 32 + lane);
#pragma unroll
        for (int off = 16; off; off >>= 1)
            r += __shfl_down_sync(0xffffffffu, r, off);
        if (lane == 0)
            out[bb * 8192 + w0 + pos] =
                ((float)ind + r + __ldg(cm3_b + ind)) * (1.0f / 128.0f);
    }
}

// ---------------- launch ----------------
extern "C" void kernel_launch(void* const* d_in, const int* in_sizes, int n_in,
                              void* d_out, int out_size)
{
    const float* x_in  = (const float*)d_in[0];
    const float* cl1_w = (const float*)d_in[1];
    const float* cl1_b = (const float*)d_in[2];
    const float* bn1_g = (const float*)d_in[3];
    const float* bn1_b = (const float*)d_in[4];
    const float* bn1_m = (const float*)d_in[5];
    const float* bn1_v = (const float*)d_in[6];
    const float* cl2_w = (const float*)d_in[7];
    const float* cl2_b = (const float*)d_in[8];
    const float* cl3_w = (const float*)d_in[9];
    const float* cl3_b = (const float*)d_in[10];
    const float* reg1_w = (const float*)d_in[11];
    const float* reg1_b = (const float*)d_in[12];
    const float* bnr_g = (const float*)d_in[13];
    const float* bnr_b = (const float*)d_in[14];
    const float* bnr_m = (const float*)d_in[15];
    const float* bnr_v = (const float*)d_in[16];
    const float* cm2_w = (const float*)d_in[17];
    const float* cm2_b = (const float*)d_in[18];
    const float* cm3_w = (const float*)d_in[19];
    const float* cm3_b = (const float*)d_in[20];
    float* out = (float*)d_out;

    const int SMEM_BYTES = (9216 + 8192 + 1024) * 4;   // 73728 B -> 3 CTAs/SM

    cudaFuncSetAttribute(fused_kernel, cudaFuncAttributeMaxDynamicSharedMemorySize,
                         SMEM_BYTES);

    prep_kernel<<<512, 256>>>(cl1_w, cl1_b, bn1_g, bn1_b, bn1_m, bn1_v,
                              cl2_w, cl2_b, cl3_w, cl3_b,
                              reg1_w, reg1_b, bnr_g, bnr_b, bnr_m, bnr_v,
                              cm2_w);

    fused_kernel<<<1024, 128, SMEM_BYTES>>>(x_in, cm2_b, cm3_w, cm3_b, out);
}